// round 5
// baseline (speedup 1.0000x reference)
#include <cuda_runtime.h>
#include <cuda_bf16.h>
#include <cstdint>

// out[b,s,d] = keep ? (emb[x[b,s],d] + pe[s,d]) * (1/0.9) : 0
// keep from JAX threefry2x32 (partitionable): key=(0,42), ctr=(0,i),
// bits = out0^out1, keep <=> bits < 0xE6666600  (== u<0.9f exactly)

// 2^r multipliers for the IMAD.WIDE rotate trick (opaque via __constant__,
// so ptxas can't strength-reduce mul.wide back to alu shifts).
// Rotation schedule: 13,15,26,6 | 17,29,16,24
__constant__ uint32_t ROTM[8] = {
    1u << 13, 1u << 15, 1u << 26, 1u << 6,
    1u << 17, 1u << 29, 1u << 16, 1u << 24
};

#define KS1 42u
#define KS2 0x1BD11BF0u

// One round on 4 interleaved chains, rotate-by-mul:
//   add (flexible pipe) + IMAD.WIDE (fma pipe) + LOP3 (alu pipe)
#define W4(mm)                                                             \
    _Pragma("unroll") for (int k = 0; k < 4; k++) {                        \
        x0[k] += x1[k];                                                    \
        unsigned long long p;                                              \
        asm("mul.wide.u32 %0, %1, %2;" : "=l"(p) : "r"(x1[k]), "r"(mm));   \
        x1[k] = ((uint32_t)p | (uint32_t)(p >> 32)) ^ x0[k];               \
    }

__device__ __forceinline__ void tf_bits4(uint32_t ctr, const uint32_t* m,
                                         uint32_t* bits) {
    uint32_t x0[4], x1[4];
#pragma unroll
    for (int k = 0; k < 4; k++) { x0[k] = 0u; x1[k] = ctr + (uint32_t)k + KS1; }
    W4(m[0]) W4(m[1]) W4(m[2]) W4(m[3])
#pragma unroll
    for (int k = 0; k < 4; k++) { x0[k] += KS1; x1[k] += KS2 + 1u; }
    W4(m[4]) W4(m[5]) W4(m[6]) W4(m[7])
#pragma unroll
    for (int k = 0; k < 4; k++) { x0[k] += KS2; x1[k] += 2u; }   // ks0==0
    W4(m[0]) W4(m[1]) W4(m[2]) W4(m[3])
#pragma unroll
    for (int k = 0; k < 4; k++) { x1[k] += KS1 + 3u; }           // ks0==0
    W4(m[4]) W4(m[5]) W4(m[6]) W4(m[7])
#pragma unroll
    for (int k = 0; k < 4; k++) { x0[k] += KS1; x1[k] += KS2 + 4u; }
    W4(m[0]) W4(m[1]) W4(m[2]) W4(m[3])
#pragma unroll
    for (int k = 0; k < 4; k++) { bits[k] = (x0[k] + KS2) ^ (x1[k] + 5u); }
}

// Block = one sequence position s (blockIdx.x), all 8 batches.
// 256 threads x 4 elems cover d in [0,1024); b-loop reuses PE.
__global__ __launch_bounds__(256) void embed_pe_drop_kernel(
    const int* __restrict__ x,
    const float* __restrict__ emb,
    float* __restrict__ out)
{
    uint32_t m[8];
#pragma unroll
    for (int k = 0; k < 8; k++) m[k] = ROTM[k];

    const uint32_t s = blockIdx.x;          // 0..2047
    const uint32_t d = threadIdx.x * 4u;    // 0..1020

    // PE once per thread, pre-scaled by 1/0.9.
    const float KNEG   = -0.02595256324130752f;   // -log2(10000)/512
    const float STEP   = 0.98217188542871857f;    // 2^KNEG
    const float INV2PI = 0.15915494309189535f;
    const float TWOPI  = 6.2831853071795865f;
    const float INVKEEP = 1.0f / 0.9f;
    const float sf = (float)s;
    const float w0 = exp2f((float)(d >> 1) * KNEG) * INV2PI;
    const float w1 = w0 * STEP;
    float pe[4];
    {
        float t0 = sf * w0, t1 = sf * w1;
        float a0 = (t0 - rintf(t0)) * TWOPI;
        float a1 = (t1 - rintf(t1)) * TWOPI;
        pe[0] = __sinf(a0) * INVKEEP; pe[1] = __cosf(a0) * INVKEEP;
        pe[2] = __sinf(a1) * INVKEEP; pe[3] = __cosf(a1) * INVKEEP;
    }

    // Preload 8 token ids (block-uniform -> broadcast loads).
    int tok[8];
#pragma unroll
    for (int b = 0; b < 8; b++) tok[b] = __ldg(x + (b << 11) + s);

    const uint32_t j0 = (s << 10) + d;      // flat idx for b = 0

#pragma unroll
    for (int b = 0; b < 8; b++) {
        const uint32_t j = j0 + (uint32_t)b * (2048u * 1024u);
        const float4 e = *reinterpret_cast<const float4*>(
            emb + ((size_t)tok[b] << 10) + d);

        uint32_t bits[4];
        tf_bits4(j, m, bits);

        // y = keep ? e*(1/0.9) + pe_scaled : 0   (FFMA + select)
        float4 y;
        y.x = (bits[0] < 0xE6666600u) ? fmaf(e.x, INVKEEP, pe[0]) : 0.0f;
        y.y = (bits[1] < 0xE6666600u) ? fmaf(e.y, INVKEEP, pe[1]) : 0.0f;
        y.z = (bits[2] < 0xE6666600u) ? fmaf(e.z, INVKEEP, pe[2]) : 0.0f;
        y.w = (bits[3] < 0xE6666600u) ? fmaf(e.w, INVKEEP, pe[3]) : 0.0f;

        *reinterpret_cast<float4*>(out + j) = y;
    }
}

extern "C" void kernel_launch(void* const* d_in, const int* in_sizes, int n_in,
                              void* d_out, int out_size) {
    const int* x;
    const float* emb;
    if (in_sizes[0] == 8 * 2048) {
        x = (const int*)d_in[0];
        emb = (const float*)d_in[1];
    } else {
        x = (const int*)d_in[1];
        emb = (const float*)d_in[0];
    }
    float* out = (float*)d_out;

    embed_pe_drop_kernel<<<2048, 256>>>(x, emb, out);
}

// round 6
// speedup vs baseline: 1.1656x; 1.1656x over previous
#include <cuda_runtime.h>
#include <cuda_bf16.h>
#include <cstdint>

// out[b,s,d] = keep ? (emb[x[b,s],d] + pe[s,d]) * (1/0.9) : 0
// keep from JAX threefry2x32 (partitionable): key=(0,42), ctr=(0,i),
// bits = out0^out1, keep <=> bits < 0xE6666600  (== u<0.9f exactly)

// 2^r multipliers for the IMAD.WIDE rotate trick (opaque via __constant__).
__constant__ uint32_t ROTM[4] = {1u << 13, 1u << 26, 1u << 17, 1u << 16};

#define KS1 42u
#define KS2 0x1BD11BF0u

// Wide round on 4 interleaved chains: add + IMAD.WIDE(fma) + LOP3(alu)
#define W4(mm)                                                             \
    _Pragma("unroll") for (int k = 0; k < 4; k++) {                        \
        x0[k] += x1[k];                                                    \
        unsigned long long p;                                              \
        asm("mul.wide.u32 %0, %1, %2;" : "=l"(p) : "r"(x1[k]), "r"(mm));   \
        x1[k] = ((uint32_t)p | (uint32_t)(p >> 32)) ^ x0[k];               \
    }

// Shift round on 4 interleaved chains: add + SHF(alu) + LOP3(alu)
#define S4(rr)                                                             \
    _Pragma("unroll") for (int k = 0; k < 4; k++) {                        \
        x0[k] += x1[k];                                                    \
        x1[k] = __funnelshift_l(x1[k], x1[k], (rr)) ^ x0[k];               \
    }

__device__ __forceinline__ void tf_bits4(uint32_t ctr, uint32_t m13,
                                         uint32_t m26, uint32_t m17,
                                         uint32_t m16, uint32_t* bits) {
    uint32_t x0[4], x1[4];
#pragma unroll
    for (int k = 0; k < 4; k++) { x0[k] = 0u; x1[k] = ctr + (uint32_t)k + KS1; }
    W4(m13) S4(15) W4(m26) S4(6)
#pragma unroll
    for (int k = 0; k < 4; k++) { x0[k] += KS1; x1[k] += KS2 + 1u; }
    W4(m17) S4(29) W4(m16) S4(24)
#pragma unroll
    for (int k = 0; k < 4; k++) { x0[k] += KS2; x1[k] += 2u; }   // ks0==0
    W4(m13) S4(15) W4(m26) S4(6)
#pragma unroll
    for (int k = 0; k < 4; k++) { x1[k] += KS1 + 3u; }           // ks0==0
    W4(m17) S4(29) W4(m16) S4(24)
#pragma unroll
    for (int k = 0; k < 4; k++) { x0[k] += KS1; x1[k] += KS2 + 4u; }
    W4(m13) S4(15) W4(m26) S4(6)
#pragma unroll
    for (int k = 0; k < 4; k++) { bits[k] = (x0[k] + KS2) ^ (x1[k] + 5u); }
}

// Block = (s, half-row). 128 threads x 4 elems cover 512 d's; loop b = 0..7
// reuses PE. Emb gathers are software-pipelined one iteration ahead.
__global__ __launch_bounds__(128) void embed_pe_drop_kernel(
    const int* __restrict__ x,
    const float* __restrict__ emb,
    float* __restrict__ out)
{
    const uint32_t m13 = ROTM[0], m26 = ROTM[1], m17 = ROTM[2], m16 = ROTM[3];

    const uint32_t s = blockIdx.x >> 1;                       // 0..2047
    const uint32_t d = ((blockIdx.x & 1u) << 9) + threadIdx.x * 4u;  // 0..1020

    // PE once per thread, pre-scaled by 1/0.9.
    const float KNEG   = -0.02595256324130752f;   // -log2(10000)/512
    const float STEP   = 0.98217188542871857f;    // 2^KNEG
    const float INV2PI = 0.15915494309189535f;
    const float TWOPI  = 6.2831853071795865f;
    const float INVKEEP = 1.0f / 0.9f;
    const float sf = (float)s;
    const float w0 = exp2f((float)(d >> 1) * KNEG) * INV2PI;
    const float w1 = w0 * STEP;
    float pe[4];
    {
        float t0 = sf * w0, t1 = sf * w1;
        float a0 = (t0 - rintf(t0)) * TWOPI;
        float a1 = (t1 - rintf(t1)) * TWOPI;
        pe[0] = __sinf(a0) * INVKEEP; pe[1] = __cosf(a0) * INVKEEP;
        pe[2] = __sinf(a1) * INVKEEP; pe[3] = __cosf(a1) * INVKEEP;
    }

    // Preload 8 token ids (block-uniform -> broadcast loads).
    int tok[8];
#pragma unroll
    for (int b = 0; b < 8; b++) tok[b] = __ldg(x + (b << 11) + s);

    const uint32_t j0 = (s << 10) + d;          // flat idx for b = 0
    const uint32_t JSTEP = 2048u * 1024u;

    // Software pipeline: gather for b+1 issued before threefry for b.
    float4 e = *reinterpret_cast<const float4*>(emb + ((size_t)tok[0] << 10) + d);

#pragma unroll
    for (int b = 0; b < 8; b++) {
        float4 enext;
        if (b < 7)
            enext = *reinterpret_cast<const float4*>(
                emb + ((size_t)tok[b + 1] << 10) + d);

        const uint32_t j = j0 + (uint32_t)b * JSTEP;
        uint32_t bits[4];
        tf_bits4(j, m13, m26, m17, m16, bits);

        float4 y;
        y.x = (bits[0] < 0xE6666600u) ? fmaf(e.x, INVKEEP, pe[0]) : 0.0f;
        y.y = (bits[1] < 0xE6666600u) ? fmaf(e.y, INVKEEP, pe[1]) : 0.0f;
        y.z = (bits[2] < 0xE6666600u) ? fmaf(e.z, INVKEEP, pe[2]) : 0.0f;
        y.w = (bits[3] < 0xE6666600u) ? fmaf(e.w, INVKEEP, pe[3]) : 0.0f;

        *reinterpret_cast<float4*>(out + j) = y;

        if (b < 7) e = enext;
    }
}

extern "C" void kernel_launch(void* const* d_in, const int* in_sizes, int n_in,
                              void* d_out, int out_size) {
    const int* x;
    const float* emb;
    if (in_sizes[0] == 8 * 2048) {
        x = (const int*)d_in[0];
        emb = (const float*)d_in[1];
    } else {
        x = (const int*)d_in[1];
        emb = (const float*)d_in[0];
    }
    float* out = (float*)d_out;

    embed_pe_drop_kernel<<<4096, 128>>>(x, emb, out);
}